// round 2
// baseline (speedup 1.0000x reference)
#include <cuda_runtime.h>
#include <math.h>

// NNLS PGD step:
//   new_X = relu(th1 @ Y + weight)
//   Y_new = new_X + (k-1)/(k+2) * (new_X - X_old)
// Outputs (flattened tuple): [Y_new (K*B) | new_X (K*B) | k+1 (1) | weight (K*B)]
//
// th1: [K,K] f32 row-major, Y/X_old/weight: [K,B] f32 row-major.

#define BM 128
#define BN 128
#define BK 8
#define TM 8
#define TN 8

__global__ __launch_bounds__(256, 2) void nnls_gemm_fused(
    const float* __restrict__ A,      // th1 [K,K]
    const float* __restrict__ Bm,     // Y   [K,N]
    const float* __restrict__ Xold,   // [K,N]
    const float* __restrict__ W,      // [K,N]
    const int*   __restrict__ kptr,   // scalar iteration counter
    float* __restrict__ Ynew,         // [K,N]
    float* __restrict__ newX,         // [K,N] (may be null)
    int K, int N)
{
    __shared__ float As[BK][BM];   // transposed A tile: As[k][m]
    __shared__ float Bs[BK][BN];   // Bs[k][n]

    const int tid = threadIdx.x;
    const int tx  = tid & 15;      // 0..15 -> column group
    const int ty  = tid >> 4;      // 0..15 -> row group
    const int bm  = blockIdx.y * BM;
    const int bn  = blockIdx.x * BN;

    // A tile load mapping: 128 rows x 8 cols = 1024 floats = 256 float4
    const int a_row  = tid >> 1;          // 0..127
    const int a_col4 = (tid & 1) * 4;     // 0 or 4
    // B tile load mapping: 8 rows x 128 cols = 256 float4
    const int b_row  = tid >> 5;          // 0..7
    const int b_col  = (tid & 31) * 4;    // 0..124

    float acc[TM][TN];
    #pragma unroll
    for (int i = 0; i < TM; i++)
        #pragma unroll
        for (int j = 0; j < TN; j++)
            acc[i][j] = 0.0f;

    const float* a_ptr = A + (size_t)(bm + a_row) * K + a_col4;
    const float* b_ptr = Bm + (size_t)b_row * N + bn + b_col;

    for (int kt = 0; kt < K; kt += BK) {
        float4 av = *(const float4*)(a_ptr + kt);
        As[a_col4 + 0][a_row] = av.x;
        As[a_col4 + 1][a_row] = av.y;
        As[a_col4 + 2][a_row] = av.z;
        As[a_col4 + 3][a_row] = av.w;

        float4 bv = *(const float4*)(b_ptr + (size_t)kt * N);
        *(float4*)&Bs[b_row][b_col] = bv;

        __syncthreads();

        #pragma unroll
        for (int k = 0; k < BK; k++) {
            float4 a0 = *(const float4*)&As[k][ty * TM];
            float4 a1 = *(const float4*)&As[k][ty * TM + 4];
            float4 b0 = *(const float4*)&Bs[k][tx * TN];
            float4 b1 = *(const float4*)&Bs[k][tx * TN + 4];
            float a[TM] = {a0.x, a0.y, a0.z, a0.w, a1.x, a1.y, a1.z, a1.w};
            float b[TN] = {b0.x, b0.y, b0.z, b0.w, b1.x, b1.y, b1.z, b1.w};
            #pragma unroll
            for (int i = 0; i < TM; i++)
                #pragma unroll
                for (int j = 0; j < TN; j++)
                    acc[i][j] = fmaf(a[i], b[j], acc[i][j]);
        }
        __syncthreads();
    }

    // Epilogue: new_X = relu(acc + W); Y_new = new_X*(1+m) - m*X_old
    const int kk = *kptr;
    const float mom = (float)(kk - 1) / (float)(kk + 2);

    #pragma unroll
    for (int i = 0; i < TM; i++) {
        const int row = bm + ty * TM + i;
        const size_t base = (size_t)row * N + bn + tx * TN;
        #pragma unroll
        for (int j4 = 0; j4 < TN; j4 += 4) {
            float4 wv = *(const float4*)(W + base + j4);
            float4 xo = *(const float4*)(Xold + base + j4);
            float4 nx, yn;
            nx.x = fmaxf(acc[i][j4 + 0] + wv.x, 0.0f);
            nx.y = fmaxf(acc[i][j4 + 1] + wv.y, 0.0f);
            nx.z = fmaxf(acc[i][j4 + 2] + wv.z, 0.0f);
            nx.w = fmaxf(acc[i][j4 + 3] + wv.w, 0.0f);
            yn.x = nx.x + mom * (nx.x - xo.x);
            yn.y = nx.y + mom * (nx.y - xo.y);
            yn.z = nx.z + mom * (nx.z - xo.z);
            yn.w = nx.w + mom * (nx.w - xo.w);
            *(float4*)(Ynew + base + j4) = yn;
            if (newX) *(float4*)(newX + base + j4) = nx;
        }
    }
}

__global__ void nnls_write_meta(float* out, const int* kptr) {
    out[0] = (float)(*kptr + 1);
}

extern "C" void kernel_launch(void* const* d_in, const int* in_sizes, int n_in,
                              void* d_out, int out_size) {
    const float* th1  = (const float*)d_in[0];
    const float* Y    = (const float*)d_in[1];
    const float* Xold = (const float*)d_in[2];
    const int*   kptr = (const int*)  d_in[3];
    const float* W    = (const float*)d_in[4];

    // Derive K, B from input sizes (th1 is K x K, Y is K x B)
    int K = 1;
    while ((long long)K * K < (long long)in_sizes[0]) K <<= 1;
    const int N = in_sizes[1] / K;
    const size_t KB = (size_t)K * N;

    float* out  = (float*)d_out;
    float* Ynew = out;
    float* newX = ((size_t)out_size >= 2 * KB) ? out + KB : nullptr;

    dim3 grid(N / BN, K / BM);
    nnls_gemm_fused<<<grid, 256>>>(th1, Y, Xold, W, kptr, Ynew, newX, K, N);

    if ((size_t)out_size >= 3 * KB + 1) {
        nnls_write_meta<<<1, 1>>>(out + 2 * KB, kptr);
        cudaMemcpyAsync(out + 2 * KB + 1, W, KB * sizeof(float),
                        cudaMemcpyDeviceToDevice);
    }
}

// round 10
// speedup vs baseline: 2.5746x; 2.5746x over previous
#include <cuda_runtime.h>
#include <cuda_bf16.h>
#include <cstdint>
#include <cstddef>

// NNLS PGD step via mma.sync bf16 x3 split GEMM (compute_103-safe: no tcgen05).
//   new_X = relu(th1 @ Y + W); Y_new = new_X + (k-1)/(k+2)*(new_X - X_old)
// Output tuple: [Y_new (K*B) | new_X (K*B) | k+1 (1) | W (K*B)]
// NOTE: W-passthrough output base is ODD (offset 2*KB+1) -> scalar stores only.

#define BM 128
#define BN 128
#define BK 32
#define OFF_AH 0u
#define OFF_AL 8192u
#define OFF_BH 16384u
#define OFF_BL 24576u
#define BUF_BYTES 32768u
#define SMEM_BYTES 65536u

static __device__ __forceinline__ uint32_t s2u(const void* p) {
    uint32_t a;
    asm("{ .reg .u64 t; cvta.to.shared.u64 t, %1; cvt.u32.u64 %0, t; }"
        : "=r"(a) : "l"(p));
    return a;
}

static __device__ __forceinline__ void ldsm4(uint32_t a, uint32_t* r) {
    asm volatile("ldmatrix.sync.aligned.m8n8.x4.shared.b16 {%0,%1,%2,%3}, [%4];"
                 : "=r"(r[0]), "=r"(r[1]), "=r"(r[2]), "=r"(r[3]) : "r"(a));
}
static __device__ __forceinline__ void ldsm4t(uint32_t a, uint32_t* r) {
    asm volatile("ldmatrix.sync.aligned.m8n8.x4.trans.shared.b16 {%0,%1,%2,%3}, [%4];"
                 : "=r"(r[0]), "=r"(r[1]), "=r"(r[2]), "=r"(r[3]) : "r"(a));
}
static __device__ __forceinline__ void mma16816(float* d, const uint32_t* a,
                                                uint32_t b0, uint32_t b1) {
    asm volatile(
        "mma.sync.aligned.m16n8k16.row.col.f32.bf16.bf16.f32 "
        "{%0,%1,%2,%3}, {%4,%5,%6,%7}, {%8,%9}, {%0,%1,%2,%3};"
        : "+f"(d[0]), "+f"(d[1]), "+f"(d[2]), "+f"(d[3])
        : "r"(a[0]), "r"(a[1]), "r"(a[2]), "r"(a[3]), "r"(b0), "r"(b1));
}

// Split float pair -> packed bf16x2 hi and lo.
static __device__ __forceinline__ void splt2(float x, float y,
                                             uint32_t& h, uint32_t& l) {
    __nv_bfloat162 H = __floats2bfloat162_rn(x, y);
    float rx = x - __bfloat162float(__low2bfloat16(H));
    float ry = y - __bfloat162float(__high2bfloat16(H));
    __nv_bfloat162 L = __floats2bfloat162_rn(rx, ry);
    h = *(uint32_t*)&H;
    l = *(uint32_t*)&L;
}

__global__ __launch_bounds__(256, 1) void nnls_mma(
    const float* __restrict__ A, const float* __restrict__ Bm,
    const float* __restrict__ Xold, const float* __restrict__ W,
    const int* __restrict__ kptr,
    float* __restrict__ Ynew, float* __restrict__ newX, float* __restrict__ Wout,
    int Kd, int Nd)
{
    extern __shared__ char smem[];
    const uint32_t sb = s2u(smem);
    const int tid = threadIdx.x, wid = tid >> 5, lane = tid & 31;
    const int warp_m = wid & 1, warp_n = wid >> 1;
    const int bm = blockIdx.y * BM, bn = blockIdx.x * BN;

    float acc[4][4][4];
    #pragma unroll
    for (int i = 0; i < 4; i++)
        #pragma unroll
        for (int j = 0; j < 4; j++)
            #pragma unroll
            for (int e = 0; e < 4; e++) acc[i][j][e] = 0.0f;

    // Global load mapping (float4). A: 4 rows-of-8 per 256 thr; B: row k, 32 f4.
    const int am = tid >> 3, aq = tid & 7;            // A: m=am(+32i), k=aq*4
    const int bk = tid >> 5, bq = tid & 31;           // B: k=bk(+8i), n=bq*4

    // STS swizzled byte offsets (per float4 -> 8B h + 8B l).
    // A: row m (64B), chunk aq>>1 (k/8), half (aq&1)*8; swz chunk ^ ((m>>1)&3)
    // B: row k (256B), chunk bq>>1 (n/8), half (bq&1)*8; swz chunk ^ (k&7)
    uint32_t a_sts[4], b_sts[4];
    #pragma unroll
    for (int i = 0; i < 4; i++) {
        int m = am + i * 32;
        a_sts[i] = (uint32_t)m * 64u
                 + ((uint32_t)(((aq >> 1) ^ ((m >> 1) & 3)) << 4))
                 + (uint32_t)((aq & 1) * 8);
        int k = bk + i * 8;
        b_sts[i] = (uint32_t)k * 256u
                 + ((uint32_t)(((bq >> 1) ^ (k & 7)) << 4))
                 + (uint32_t)((bq & 1) * 8);
    }

    // ldmatrix per-lane invariants.
    const int arow = warp_m * 64 + (lane & 15);       // + mi*16
    const uint32_t s_a = (uint32_t)((arow >> 1) & 3);
    const uint32_t a_base = (uint32_t)arow * 64u;     // FIX: no sb here (buf has it)
    const int brow15 = lane & 15;                     // + ks*16
    const uint32_t s_b = (uint32_t)(lane & 7);
    const uint32_t kc_hi = (uint32_t)(lane >> 4);     // 0/1: chunk offset add

    float4 ar[4], br[4];
    #pragma unroll
    for (int i = 0; i < 4; i++) {
        ar[i] = *(const float4*)(A + (size_t)(bm + am + i * 32) * Kd + aq * 4);
        br[i] = *(const float4*)(Bm + (size_t)(bk + i * 8) * Nd + bn + bq * 4);
    }

    const int NIT = Kd / BK;  // 32
    for (int c = 0; c < NIT; c++) {
        const uint32_t buf = sb + (uint32_t)(c & 1) * BUF_BYTES;
        const uint32_t bufo = (uint32_t)(c & 1) * BUF_BYTES;

        // split + STS
        #pragma unroll
        for (int i = 0; i < 4; i++) {
            uint2 h, l;
            splt2(ar[i].x, ar[i].y, h.x, l.x);
            splt2(ar[i].z, ar[i].w, h.y, l.y);
            *(uint2*)(smem + bufo + OFF_AH + a_sts[i]) = h;
            *(uint2*)(smem + bufo + OFF_AL + a_sts[i]) = l;
            splt2(br[i].x, br[i].y, h.x, l.x);
            splt2(br[i].z, br[i].w, h.y, l.y);
            *(uint2*)(smem + bufo + OFF_BH + b_sts[i]) = h;
            *(uint2*)(smem + bufo + OFF_BL + b_sts[i]) = l;
        }
        __syncthreads();

        // prefetch next k-tile
        if (c + 1 < NIT) {
            const int kt = (c + 1) * BK;
            #pragma unroll
            for (int i = 0; i < 4; i++) {
                ar[i] = *(const float4*)(A + (size_t)(bm + am + i * 32) * Kd + kt + aq * 4);
                br[i] = *(const float4*)(Bm + (size_t)(kt + bk + i * 8) * Nd + bn + bq * 4);
            }
        }

        // compute: 2 k-steps x 3 passes x 16 mmas
        #pragma unroll
        for (int ks = 0; ks < 2; ks++) {
            uint32_t ah[4][4], al[4][4], bh[2][4], bl[2][4];
            const uint32_t a_sw = ((uint32_t)(ks * 2) + kc_hi) ^ s_a;
            #pragma unroll
            for (int mi = 0; mi < 4; mi++) {
                uint32_t addr = buf + a_base + (uint32_t)mi * 1024u + (a_sw << 4);
                ldsm4(addr + OFF_AH, ah[mi]);
                ldsm4(addr + OFF_AL, al[mi]);
            }
            const uint32_t brow = (uint32_t)(ks * 16 + brow15) * 256u;
            #pragma unroll
            for (int nt = 0; nt < 2; nt++) {
                uint32_t nc = (uint32_t)(warp_n * 4 + nt * 2) + kc_hi;
                uint32_t addr = buf + brow + ((nc ^ s_b) << 4);
                ldsm4t(addr + OFF_BH, bh[nt]);
                ldsm4t(addr + OFF_BL, bl[nt]);
            }
            #pragma unroll
            for (int mi = 0; mi < 4; mi++)
                #pragma unroll
                for (int ni = 0; ni < 4; ni++) {
                    const int nt = ni >> 1, pr = (ni & 1) * 2;
                    mma16816(acc[mi][ni], ah[mi], bh[nt][pr], bh[nt][pr + 1]);
                    mma16816(acc[mi][ni], ah[mi], bl[nt][pr], bl[nt][pr + 1]);
                    mma16816(acc[mi][ni], al[mi], bh[nt][pr], bh[nt][pr + 1]);
                }
        }
        __syncthreads();
    }

    // Fused epilogue from registers.
    const int kk = *kptr;
    const float mom = (float)(kk - 1) / (float)(kk + 2);
    #pragma unroll
    for (int mi = 0; mi < 4; mi++) {
        const int row0 = bm + warp_m * 64 + mi * 16 + (lane >> 2);
        #pragma unroll
        for (int ni = 0; ni < 4; ni++) {
            const int col = bn + warp_n * 32 + ni * 8 + (lane & 3) * 2;
            #pragma unroll
            for (int h = 0; h < 2; h++) {
                const size_t gi = (size_t)(row0 + h * 8) * Nd + col;
                float2 wv = *(const float2*)(W + gi);
                float2 xo = *(const float2*)(Xold + gi);
                float2 nx, yn;
                nx.x = fmaxf(acc[mi][ni][h * 2 + 0] + wv.x, 0.0f);
                nx.y = fmaxf(acc[mi][ni][h * 2 + 1] + wv.y, 0.0f);
                yn.x = nx.x + mom * (nx.x - xo.x);
                yn.y = nx.y + mom * (nx.y - xo.y);
                *(float2*)(Ynew + gi) = yn;
                *(float2*)(newX + gi) = nx;
                // Wout base is odd-float-offset: 4B-aligned only -> scalar stores
                Wout[gi]     = wv.x;
                Wout[gi + 1] = wv.y;
            }
        }
    }
}

__global__ void nnls_meta(float* out, const int* kptr) {
    out[0] = (float)(*kptr + 1);
}

extern "C" void kernel_launch(void* const* d_in, const int* in_sizes, int n_in,
                              void* d_out, int out_size) {
    const float* th1  = (const float*)d_in[0];
    const float* Y    = (const float*)d_in[1];
    const float* Xold = (const float*)d_in[2];
    const int*   kptr = (const int*)  d_in[3];
    const float* W    = (const float*)d_in[4];

    int K = 1;
    while ((long long)K * K < (long long)in_sizes[0]) K <<= 1;
    const int N = in_sizes[1] / K;
    const size_t KB = (size_t)K * N;

    float* out = (float*)d_out;
    cudaFuncSetAttribute(nnls_mma, cudaFuncAttributeMaxDynamicSharedMemorySize,
                         SMEM_BYTES);
    dim3 grid(N / BN, K / BM);
    nnls_mma<<<grid, 256, SMEM_BYTES>>>(th1, Y, Xold, W, kptr,
                                        out, out + KB, out + 2 * KB + 1, K, N);
    nnls_meta<<<1, 1>>>(out + 2 * KB, kptr);
}